// round 13
// baseline (speedup 1.0000x reference)
#include <cuda_runtime.h>
#include <cuda_fp16.h>
#include <float.h>
#include <stdint.h>

// ---------------------------------------------------------------------------
// Problem constants (fixed shapes for SparseVLMModel_59725815218738)
// ---------------------------------------------------------------------------
#define B_SZ    64
#define S_SZ    197
#define P_SZ    196
#define T_SZ    512
#define DV      768
#define DL      4096
#define TOPK    32
#define OUT_S   (TOPK + T_SZ)   // 544
#define LN_EPS  1e-5f
#define VOCAB   32000
#define NROWS   (B_SZ * T_SZ)   // 32768

#define M_TOT   (B_SZ * TOPK)   // 2048
#define KC      DV              // 768: plain fp16 GEMM (A,B rounded to fp16)
#define TM      128
#define TN      128
#define KCHUNK  64
#define NCHUNK  (KC / KCHUNK)   // 12

// Scratch (no cudaMalloc allowed)
__device__ float g_scores[B_SZ * P_SZ];
__device__ int   g_topk[M_TOT];
__device__ int   g_hist[VOCAB];
__device__ int   g_perm[NROWS];
__device__ __align__(128) __half g_A[(size_t)M_TOT * KC]; // 3.1 MB
__device__ __align__(128) __half g_B[(size_t)DL * KC];    // 6.3 MB

__device__ __forceinline__ uint32_t smem_u32(const void* p) {
    uint32_t a;
    asm("{ .reg .u64 t; cvta.to.shared.u64 t, %1; cvt.u32.u64 %0, t; }" : "=r"(a) : "l"(p));
    return a;
}
__device__ __forceinline__ void ldsm4(uint32_t* r, uint32_t addr) {
    asm volatile("ldmatrix.sync.aligned.m8n8.x4.shared.b16 {%0,%1,%2,%3}, [%4];"
                 : "=r"(r[0]), "=r"(r[1]), "=r"(r[2]), "=r"(r[3]) : "r"(addr));
}
__device__ __forceinline__ void mma_f16(float* c, const uint32_t* a,
                                        uint32_t b0, uint32_t b1) {
    asm volatile(
        "mma.sync.aligned.m16n8k16.row.col.f32.f16.f16.f32 "
        "{%0,%1,%2,%3}, {%4,%5,%6,%7}, {%8,%9}, {%0,%1,%2,%3};"
        : "+f"(c[0]), "+f"(c[1]), "+f"(c[2]), "+f"(c[3])
        : "r"(a[0]), "r"(a[1]), "r"(a[2]), "r"(a[3]), "r"(b0), "r"(b1));
}
__device__ __forceinline__ void cp16(uint32_t saddr, const void* g) {
    asm volatile("cp.async.cg.shared.global [%0], [%1], 16;"
                 :: "r"(saddr), "l"(g) : "memory");
}
#define CP_COMMIT() asm volatile("cp.async.commit_group;" ::: "memory")
#define CP_WAIT2()  asm volatile("cp.async.wait_group 2;" ::: "memory")
#define SW128(x) ((x) ^ (((x) >> 3) & 0x70))

// Per-block int64/int32 sniff: ids < 32000, so int64 => all odd words zero.
__device__ __forceinline__ int sniff_is64(const int* __restrict__ ids32) {
    unsigned nz = __ballot_sync(0xffffffffu,
                                ids32[2 * (threadIdx.x & 31) + 1] != 0);
    return (nz == 0u) ? 1 : 0;
}
__device__ __forceinline__ long long load_id(const int* __restrict__ ids32,
                                             int r, int is64) {
    return is64 ? ((const long long*)ids32)[r] : (long long)ids32[r];
}

// ---------------------------------------------------------------------------
// 1. Scores: warp-per-row LayerNorm dot (ordering-equivalent form)
// ---------------------------------------------------------------------------
__global__ void __launch_bounds__(256)
scores_kernel(const float* __restrict__ vt,
              const float* __restrict__ gamma,
              const float* __restrict__ w) {
    int warp = (blockIdx.x * 256 + threadIdx.x) >> 5;
    int lane = threadIdx.x & 31;
    if (warp >= B_SZ * P_SZ) return;
    int b = warp / P_SZ, s = warp % P_SZ;
    const float4* x4 = (const float4*)(vt + (size_t)(b * S_SZ + 1 + s) * DV);
    const float4* g4 = (const float4*)gamma;
    const float4* w4 = (const float4*)w;

    float s1 = 0.f, s2 = 0.f, sgw = 0.f, cgw = 0.f;
    #pragma unroll
    for (int i = 0; i < 6; i++) {
        int idx = lane + i * 32;
        float4 xv = x4[idx];
        float4 gv = g4[idx];
        float4 wv = w4[idx];
        float gw0 = gv.x * wv.x, gw1 = gv.y * wv.y, gw2 = gv.z * wv.z, gw3 = gv.w * wv.w;
        s1 += xv.x + xv.y + xv.z + xv.w;
        s2 += xv.x * xv.x + xv.y * xv.y + xv.z * xv.z + xv.w * xv.w;
        sgw += xv.x * gw0 + xv.y * gw1 + xv.z * gw2 + xv.w * gw3;
        cgw += gw0 + gw1 + gw2 + gw3;
    }
    #pragma unroll
    for (int st = 16; st > 0; st >>= 1) {
        s1  += __shfl_xor_sync(0xffffffffu, s1, st);
        s2  += __shfl_xor_sync(0xffffffffu, s2, st);
        sgw += __shfl_xor_sync(0xffffffffu, sgw, st);
        cgw += __shfl_xor_sync(0xffffffffu, cgw, st);
    }
    if (lane == 0) {
        float mean = s1 * (1.0f / DV);
        float var  = s2 * (1.0f / DV) - mean * mean;
        float rstd = rsqrtf(var + LN_EPS);
        g_scores[warp] = rstd * (sgw - mean * cgw);
    }
}

// ---------------------------------------------------------------------------
// 2. Top-32 per batch: warp-per-batch register argmax, stable ties.
// ---------------------------------------------------------------------------
__global__ void __launch_bounds__(256)
topk_kernel() {
    int warp = (blockIdx.x * 256 + threadIdx.x) >> 5;   // 0..63
    int lane = threadIdx.x & 31;
    if (warp >= B_SZ) return;
    float v[7];
    #pragma unroll
    for (int i = 0; i < 7; i++) {
        int idx = lane + i * 32;
        v[i] = (idx < P_SZ) ? g_scores[warp * P_SZ + idx] : -FLT_MAX;
    }
    for (int k = 0; k < TOPK; k++) {
        float best = -FLT_MAX; int bi = 0;
        #pragma unroll
        for (int i = 0; i < 7; i++)
            if (v[i] > best) { best = v[i]; bi = i; }    // ascending idx: stable
        int bidx = lane + bi * 32;
        #pragma unroll
        for (int st = 16; st > 0; st >>= 1) {
            float ov = __shfl_xor_sync(0xffffffffu, best, st);
            int   oi = __shfl_xor_sync(0xffffffffu, bidx, st);
            if (ov > best || (ov == best && oi < bidx)) { best = ov; bidx = oi; }
        }
        if (lane == 0) g_topk[warp * TOPK + k] = bidx;
        if ((bidx & 31) == lane) v[bidx >> 5] = -FLT_MAX;
    }
}

// ---------------------------------------------------------------------------
// 3a. Convert gathered A rows fp32 -> fp16 (single term, K = 768)
// ---------------------------------------------------------------------------
__global__ void __launch_bounds__(128)
convertA_kernel(const float* __restrict__ vt) {
    int m = blockIdx.x;                // 0..2047
    int b = m >> 5;
    size_t base = (size_t)(b * S_SZ + 1 + g_topk[m]) * DV;
    __half* rowA = g_A + (size_t)m * KC;
    int t = threadIdx.x;
    #pragma unroll
    for (int i = 0; i < 3; i++) {
        int p = t + i * 128;           // pair 0..383
        float v0 = vt[base + 2 * p], v1 = vt[base + 2 * p + 1];
        __half2 hp;
        hp.x = __float2half_rn(v0);
        hp.y = __float2half_rn(v1);
        *(__half2*)(rowA + 2 * p) = hp;
    }
}

// ---------------------------------------------------------------------------
// 3b. Convert+transpose proj_w [768,4096] -> g_B [4096][768] fp16
// ---------------------------------------------------------------------------
__global__ void __launch_bounds__(256)
convertB_kernel(const float* __restrict__ W) {
    __shared__ float tile[32][33];
    int n0 = blockIdx.x * 32;          // 128 blocks
    int k0 = blockIdx.y * 32;          // 24 blocks
    int t = threadIdx.x;
    #pragma unroll
    for (int i = 0; i < 4; i++) {
        int e = t + i * 256;
        int r = e >> 5, c = e & 31;
        tile[r][c] = W[(size_t)(k0 + r) * DL + n0 + c];
    }
    __syncthreads();
    #pragma unroll
    for (int i = 0; i < 2; i++) {
        int n = (t >> 4) + i * 16;
        int j = t & 15;
        __half2 hp;
        hp.x = __float2half_rn(tile[2 * j][n]);
        hp.y = __float2half_rn(tile[2 * j + 1][n]);
        *(__half2*)(g_B + (size_t)(n0 + n) * KC + k0 + 2 * j) = hp;
    }
}

// ---------------------------------------------------------------------------
// 4. mma.sync GEMM: D[2048,4096] = A[2048,768] @ B[4096,768]^T + bias
//    128x128 tile/CTA, 8 warps x (64x32), KCHUNK=64, SW128 smem,
//    3-stage cp.async pipeline, 2 CTAs/SM, CTA-swizzled for L2 locality.
// ---------------------------------------------------------------------------
#define STAGE_BYTES 32768
#define SA_OFF(st) ((st) * STAGE_BYTES)
#define SB_OFF(st) ((st) * STAGE_BYTES + 16384)
#define SMEM_TOTAL (3 * STAGE_BYTES)    // 96 KB

__global__ void __launch_bounds__(256, 2)
gemm_mma_kernel(const float* __restrict__ bias, float* __restrict__ out) {
    extern __shared__ __align__(1024) char smem[];
    uint32_t sbase = smem_u32(smem);
    int tid = threadIdx.x;
    int wid = tid >> 5, lane = tid & 31;
    // swizzle: mblk inner -> 296 concurrent CTAs share all of A + ~18 B tiles
    int mblk = blockIdx.x & 15;          // 16
    int nblk = blockIdx.x >> 4;          // 32
    int m0 = mblk * TM, n0 = nblk * TN;
    int wm = (wid & 1) * 64;             // warp M offset
    int wn = (wid >> 1) * 32;            // warp N offset

    const __half* Abase = g_A + (size_t)m0 * KC;
    const __half* Bbase = g_B + (size_t)n0 * KC;

    // ldmatrix lane addressing
    int q = lane >> 3, r8 = lane & 7;
    int qm = (q & 1) * 8;
    int qk = (q >> 1) * 16;

    float acc[4][4][4];
    #pragma unroll
    for (int a = 0; a < 4; a++)
        #pragma unroll
        for (int b = 0; b < 4; b++)
            #pragma unroll
            for (int c = 0; c < 4; c++) acc[a][b][c] = 0.f;

    #define ISSUE(cc) do { \
        int _stg = (cc) % 3; \
        const __half* Ap = Abase + (size_t)(cc) * KCHUNK; \
        const __half* Bp = Bbase + (size_t)(cc) * KCHUNK; \
        _Pragma("unroll") \
        for (int i = 0; i < 4; i++) { \
            int f = tid + i * 256; \
            int row = f >> 3, j = f & 7; \
            int off = SW128(row * 128 + j * 16); \
            cp16(sbase + SA_OFF(_stg) + off, Ap + (size_t)row * KC + j * 8); \
            cp16(sbase + SB_OFF(_stg) + off, Bp + (size_t)row * KC + j * 8); \
        } \
    } while (0)

    ISSUE(0); CP_COMMIT();
    ISSUE(1); CP_COMMIT();

    #pragma unroll 1
    for (int c = 0; c < NCHUNK; c++) {
        if (c + 2 < NCHUNK) ISSUE(c + 2);
        CP_COMMIT();
        CP_WAIT2();                      // stage c's group complete
        __syncthreads();

        int st = c % 3;
        uint32_t abuf = sbase + SA_OFF(st);
        uint32_t bbuf = sbase + SB_OFF(st);
        #pragma unroll
        for (int ks = 0; ks < 4; ks++) {
            uint32_t afr[4][4], bfr[2][4];
            #pragma unroll
            for (int mt = 0; mt < 4; mt++)
                ldsm4(afr[mt], abuf + SW128((wm + mt * 16 + qm + r8) * 128 + ks * 32 + qk));
            #pragma unroll
            for (int nt = 0; nt < 2; nt++)
                ldsm4(bfr[nt], bbuf + SW128((wn + nt * 16 + qm + r8) * 128 + ks * 32 + qk));
            #pragma unroll
            for (int mt = 0; mt < 4; mt++)
                #pragma unroll
                for (int nf = 0; nf < 4; nf++) {
                    int nt = nf >> 1, half = nf & 1;
                    mma_f16(acc[mt][nf], afr[mt], bfr[nt][half], bfr[nt][half + 2]);
                }
        }
        __syncthreads();                 // all reads of buf st done
    }

    // epilogue: C frag m16n8: c0,c1=(row g, col 2i,2i+1); c2,c3=(row g+8)
    int g = lane >> 2, i2 = (lane & 3) * 2;
    #pragma unroll
    for (int mt = 0; mt < 4; mt++) {
        #pragma unroll
        for (int rh = 0; rh < 2; rh++) {
            int m = m0 + wm + mt * 16 + rh * 8 + g;
            int b = m >> 5, kk = m & 31;
            float* orow = out + (size_t)(b * OUT_S + kk) * DL + n0 + wn;
            #pragma unroll
            for (int nf = 0; nf < 4; nf++) {
                int n = nf * 8 + i2;
                float2 bb = *(const float2*)(bias + n0 + wn + n);
                float2 o;
                o.x = acc[mt][nf][rh * 2 + 0] + bb.x;
                o.y = acc[mt][nf][rh * 2 + 1] + bb.y;
                *(float2*)(orow + n) = o;
            }
        }
    }
}

// ---------------------------------------------------------------------------
// 5a-5d. Counting sort of rows by id -> g_perm (ascending id order).
//    Duplicate ids land adjacent => gather's second read L2-hits, and the
//    table read stream becomes quasi-sequential. Within-id order is
//    nondeterministic (atomics) but harmless: identical source bytes.
// ---------------------------------------------------------------------------
__global__ void __launch_bounds__(256)
hist_zero_kernel() {
    int i = blockIdx.x * 256 + threadIdx.x;
    if (i < VOCAB) g_hist[i] = 0;
}
__global__ void __launch_bounds__(256)
hist_count_kernel(const int* __restrict__ ids32) {
    int is64 = sniff_is64(ids32);
    int r = blockIdx.x * 256 + threadIdx.x;
    if (r < NROWS) atomicAdd(&g_hist[(int)load_id(ids32, r, is64)], 1);
}
__global__ void __launch_bounds__(1024)
hist_scan_kernel() {
    __shared__ int ssum[1024];
    int t = threadIdx.x;
    int cnt[32];
    int base = t * 32;
    int local = 0;
    #pragma unroll
    for (int i = 0; i < 32; i++) {
        int idx = base + i;
        cnt[i] = (idx < VOCAB) ? g_hist[idx] : 0;
        local += cnt[i];
    }
    ssum[t] = local;
    __syncthreads();
    // Kogge-Stone inclusive scan over 1024 partials
    for (int st = 1; st < 1024; st <<= 1) {
        int v = (t >= st) ? ssum[t - st] : 0;
        __syncthreads();
        ssum[t] += v;
        __syncthreads();
    }
    int run = (t > 0) ? ssum[t - 1] : 0;   // exclusive prefix of this chunk
    #pragma unroll
    for (int i = 0; i < 32; i++) {
        int idx = base + i;
        if (idx < VOCAB) g_hist[idx] = run;
        run += cnt[i];
    }
}
__global__ void __launch_bounds__(256)
scatter_kernel(const int* __restrict__ ids32) {
    int is64 = sniff_is64(ids32);
    int r = blockIdx.x * 256 + threadIdx.x;
    if (r < NROWS) {
        int pos = atomicAdd(&g_hist[(int)load_id(ids32, r, is64)], 1);
        g_perm[pos] = r;
    }
}

// ---------------------------------------------------------------------------
// 5e. Embedding gather in id-sorted order: persistent grid-stride,
//     4 rows/iter, cached reads (adjacent duplicates hit L2), streaming
//     stores.
// ---------------------------------------------------------------------------
#define GATHER_BLOCKS 1184   // 148 SMs x 8 resident blocks
__global__ void __launch_bounds__(256)
gather_kernel(const int* __restrict__ ids32,
              const float* __restrict__ table,
              float* __restrict__ out) {
    __shared__ int s_is64;
    int tid = threadIdx.x;
    if (tid < 32) {
        int v = sniff_is64(ids32);
        if (tid == 0) s_is64 = v;
    }
    __syncthreads();
    int is64 = s_is64;

    for (int i0 = blockIdx.x * 4; i0 < NROWS; i0 += GATHER_BLOCKS * 4) {
        const float4* src[4];
        float4* dst[4];
        #pragma unroll
        for (int k = 0; k < 4; k++) {
            int r = g_perm[i0 + k];
            long long id = load_id(ids32, r, is64);
            src[k] = (const float4*)(table + (size_t)id * DL);
            dst[k] = (float4*)(out + (size_t)((r >> 9) * OUT_S + TOPK + (r & 511)) * DL);
        }
        float4 v[4][4];
        #pragma unroll
        for (int k = 0; k < 4; k++)
            #pragma unroll
            for (int i = 0; i < 4; i++)
                v[k][i] = src[k][tid + i * 256];
        #pragma unroll
        for (int k = 0; k < 4; k++)
            #pragma unroll
            for (int i = 0; i < 4; i++)
                __stcs(dst[k] + tid + i * 256, v[k][i]);
    }
}

// ---------------------------------------------------------------------------
// kernel_launch: fork immediately; s2 = sort chain -> gather, s3 = convertB,
// main = scores -> topk -> convA -> (wait convertB) -> cp.async mma GEMM.
// metadata order: vision_tokens, input_ids, ln_gamma, ln_beta, scorer_w,
//                 scorer_b, proj_w, proj_b, embed_table
// ---------------------------------------------------------------------------
extern "C" void kernel_launch(void* const* d_in, const int* in_sizes, int n_in,
                              void* d_out, int out_size) {
    const float* vision_tokens = (const float*)d_in[0];
    const void*  input_ids     = d_in[1];
    const float* ln_gamma      = (const float*)d_in[2];
    const float* scorer_w      = (const float*)d_in[4];
    const float* proj_w        = (const float*)d_in[6];
    const float* proj_b        = (const float*)d_in[7];
    const float* embed_table   = (const float*)d_in[8];
    float* out = (float*)d_out;

    static cudaStream_t s2 = nullptr, s3 = nullptr;
    static cudaEvent_t eFork = nullptr, eB = nullptr, eG = nullptr;
    if (s2 == nullptr) {
        cudaStreamCreateWithFlags(&s2, cudaStreamNonBlocking);
        cudaStreamCreateWithFlags(&s3, cudaStreamNonBlocking);
        cudaEventCreateWithFlags(&eFork, cudaEventDisableTiming);
        cudaEventCreateWithFlags(&eB, cudaEventDisableTiming);
        cudaEventCreateWithFlags(&eG, cudaEventDisableTiming);
        cudaFuncSetAttribute(gemm_mma_kernel,
                             cudaFuncAttributeMaxDynamicSharedMemorySize, SMEM_TOTAL);
    }

    cudaEventRecord(eFork, 0);
    cudaStreamWaitEvent(s2, eFork, 0);
    cudaStreamWaitEvent(s3, eFork, 0);

    // stream s2: counting sort by id, then the DRAM-bound gather
    const int* ids32 = (const int*)input_ids;
    hist_zero_kernel<<<(VOCAB + 255) / 256, 256, 0, s2>>>();
    hist_count_kernel<<<(NROWS + 255) / 256, 256, 0, s2>>>(ids32);
    hist_scan_kernel<<<1, 1024, 0, s2>>>();
    scatter_kernel<<<(NROWS + 255) / 256, 256, 0, s2>>>(ids32);
    gather_kernel<<<GATHER_BLOCKS, 256, 0, s2>>>(ids32, embed_table, out);
    cudaEventRecord(eG, s2);

    // stream s3: B conversion for the GEMM
    {
        dim3 gb(DL / 32, DV / 32);    // 128 x 24
        convertB_kernel<<<gb, 256, 0, s3>>>(proj_w);
    }
    cudaEventRecord(eB, s3);

    // main stream: scoring chain -> GEMM
    scores_kernel<<<(B_SZ * P_SZ * 32 + 255) / 256, 256>>>(vision_tokens, ln_gamma, scorer_w);
    topk_kernel<<<(B_SZ * 32 + 255) / 256, 256>>>();
    convertA_kernel<<<M_TOT, 128>>>(vision_tokens);
    cudaStreamWaitEvent(0, eB, 0);
    gemm_mma_kernel<<<(M_TOT / TM) * (DL / TN), 256, SMEM_TOTAL>>>(proj_b, out);

    cudaStreamWaitEvent(0, eG, 0);
}

// round 14
// speedup vs baseline: 1.0057x; 1.0057x over previous
#include <cuda_runtime.h>
#include <cuda_fp16.h>
#include <float.h>
#include <stdint.h>

// ---------------------------------------------------------------------------
// Problem constants (fixed shapes for SparseVLMModel_59725815218738)
// ---------------------------------------------------------------------------
#define B_SZ    64
#define S_SZ    197
#define P_SZ    196
#define T_SZ    512
#define DV      768
#define DL      4096
#define TOPK    32
#define OUT_S   (TOPK + T_SZ)   // 544
#define LN_EPS  1e-5f
#define VOCAB   32000
#define NROWS   (B_SZ * T_SZ)   // 32768

#define M_TOT   (B_SZ * TOPK)   // 2048
#define KC      DV              // 768: plain fp16 GEMM (A,B rounded to fp16)
#define TM      128
#define TN      128
#define KCHUNK  64
#define NCHUNK  (KC / KCHUNK)   // 12

// Scratch (no cudaMalloc allowed)
__device__ float g_scores[B_SZ * P_SZ];
__device__ int   g_topk[M_TOT];
__device__ int   g_hist[VOCAB];
__device__ int   g_perm[NROWS];
__device__ __align__(128) __half g_A[(size_t)M_TOT * KC]; // 3.1 MB
__device__ __align__(128) __half g_B[(size_t)DL * KC];    // 6.3 MB

__device__ __forceinline__ uint32_t smem_u32(const void* p) {
    uint32_t a;
    asm("{ .reg .u64 t; cvta.to.shared.u64 t, %1; cvt.u32.u64 %0, t; }" : "=r"(a) : "l"(p));
    return a;
}
__device__ __forceinline__ void ldsm4(uint32_t* r, uint32_t addr) {
    asm volatile("ldmatrix.sync.aligned.m8n8.x4.shared.b16 {%0,%1,%2,%3}, [%4];"
                 : "=r"(r[0]), "=r"(r[1]), "=r"(r[2]), "=r"(r[3]) : "r"(addr));
}
__device__ __forceinline__ void mma_f16(float* c, const uint32_t* a,
                                        uint32_t b0, uint32_t b1) {
    asm volatile(
        "mma.sync.aligned.m16n8k16.row.col.f32.f16.f16.f32 "
        "{%0,%1,%2,%3}, {%4,%5,%6,%7}, {%8,%9}, {%0,%1,%2,%3};"
        : "+f"(c[0]), "+f"(c[1]), "+f"(c[2]), "+f"(c[3])
        : "r"(a[0]), "r"(a[1]), "r"(a[2]), "r"(a[3]), "r"(b0), "r"(b1));
}
__device__ __forceinline__ void cp16(uint32_t saddr, const void* g) {
    asm volatile("cp.async.cg.shared.global [%0], [%1], 16;"
                 :: "r"(saddr), "l"(g) : "memory");
}
#define CP_COMMIT() asm volatile("cp.async.commit_group;" ::: "memory")
#define CP_WAIT2()  asm volatile("cp.async.wait_group 2;" ::: "memory")
#define SW128(x) ((x) ^ (((x) >> 3) & 0x70))

// Per-block int64/int32 sniff: ids < 32000, so int64 => all odd words zero.
__device__ __forceinline__ int sniff_is64(const int* __restrict__ ids32) {
    unsigned nz = __ballot_sync(0xffffffffu,
                                ids32[2 * (threadIdx.x & 31) + 1] != 0);
    return (nz == 0u) ? 1 : 0;
}
__device__ __forceinline__ long long load_id(const int* __restrict__ ids32,
                                             int r, int is64) {
    return is64 ? ((const long long*)ids32)[r] : (long long)ids32[r];
}

// ---------------------------------------------------------------------------
// 1. Scores: warp-per-row LayerNorm dot (ordering-equivalent form)
// ---------------------------------------------------------------------------
__global__ void __launch_bounds__(256)
scores_kernel(const float* __restrict__ vt,
              const float* __restrict__ gamma,
              const float* __restrict__ w) {
    int warp = (blockIdx.x * 256 + threadIdx.x) >> 5;
    int lane = threadIdx.x & 31;
    if (warp >= B_SZ * P_SZ) return;
    int b = warp / P_SZ, s = warp % P_SZ;
    const float4* x4 = (const float4*)(vt + (size_t)(b * S_SZ + 1 + s) * DV);
    const float4* g4 = (const float4*)gamma;
    const float4* w4 = (const float4*)w;

    float s1 = 0.f, s2 = 0.f, sgw = 0.f, cgw = 0.f;
    #pragma unroll
    for (int i = 0; i < 6; i++) {
        int idx = lane + i * 32;
        float4 xv = x4[idx];
        float4 gv = g4[idx];
        float4 wv = w4[idx];
        float gw0 = gv.x * wv.x, gw1 = gv.y * wv.y, gw2 = gv.z * wv.z, gw3 = gv.w * wv.w;
        s1 += xv.x + xv.y + xv.z + xv.w;
        s2 += xv.x * xv.x + xv.y * xv.y + xv.z * xv.z + xv.w * xv.w;
        sgw += xv.x * gw0 + xv.y * gw1 + xv.z * gw2 + xv.w * gw3;
        cgw += gw0 + gw1 + gw2 + gw3;
    }
    #pragma unroll
    for (int st = 16; st > 0; st >>= 1) {
        s1  += __shfl_xor_sync(0xffffffffu, s1, st);
        s2  += __shfl_xor_sync(0xffffffffu, s2, st);
        sgw += __shfl_xor_sync(0xffffffffu, sgw, st);
        cgw += __shfl_xor_sync(0xffffffffu, cgw, st);
    }
    if (lane == 0) {
        float mean = s1 * (1.0f / DV);
        float var  = s2 * (1.0f / DV) - mean * mean;
        float rstd = rsqrtf(var + LN_EPS);
        g_scores[warp] = rstd * (sgw - mean * cgw);
    }
}

// ---------------------------------------------------------------------------
// 2. Top-32 per batch: warp-per-batch register argmax, stable ties.
// ---------------------------------------------------------------------------
__global__ void __launch_bounds__(256)
topk_kernel() {
    int warp = (blockIdx.x * 256 + threadIdx.x) >> 5;   // 0..63
    int lane = threadIdx.x & 31;
    if (warp >= B_SZ) return;
    float v[7];
    #pragma unroll
    for (int i = 0; i < 7; i++) {
        int idx = lane + i * 32;
        v[i] = (idx < P_SZ) ? g_scores[warp * P_SZ + idx] : -FLT_MAX;
    }
    for (int k = 0; k < TOPK; k++) {
        float best = -FLT_MAX; int bi = 0;
        #pragma unroll
        for (int i = 0; i < 7; i++)
            if (v[i] > best) { best = v[i]; bi = i; }    // ascending idx: stable
        int bidx = lane + bi * 32;
        #pragma unroll
        for (int st = 16; st > 0; st >>= 1) {
            float ov = __shfl_xor_sync(0xffffffffu, best, st);
            int   oi = __shfl_xor_sync(0xffffffffu, bidx, st);
            if (ov > best || (ov == best && oi < bidx)) { best = ov; bidx = oi; }
        }
        if (lane == 0) g_topk[warp * TOPK + k] = bidx;
        if ((bidx & 31) == lane) v[bidx >> 5] = -FLT_MAX;
    }
}

// ---------------------------------------------------------------------------
// 3a. Convert gathered A rows fp32 -> fp16 (single term, K = 768)
// ---------------------------------------------------------------------------
__global__ void __launch_bounds__(128)
convertA_kernel(const float* __restrict__ vt) {
    int m = blockIdx.x;                // 0..2047
    int b = m >> 5;
    size_t base = (size_t)(b * S_SZ + 1 + g_topk[m]) * DV;
    __half* rowA = g_A + (size_t)m * KC;
    int t = threadIdx.x;
    #pragma unroll
    for (int i = 0; i < 3; i++) {
        int p = t + i * 128;           // pair 0..383
        float v0 = vt[base + 2 * p], v1 = vt[base + 2 * p + 1];
        __half2 hp;
        hp.x = __float2half_rn(v0);
        hp.y = __float2half_rn(v1);
        *(__half2*)(rowA + 2 * p) = hp;
    }
}

// ---------------------------------------------------------------------------
// 3b. Convert+transpose proj_w [768,4096] -> g_B [4096][768] fp16
// ---------------------------------------------------------------------------
__global__ void __launch_bounds__(256)
convertB_kernel(const float* __restrict__ W) {
    __shared__ float tile[32][33];
    int n0 = blockIdx.x * 32;          // 128 blocks
    int k0 = blockIdx.y * 32;          // 24 blocks
    int t = threadIdx.x;
    #pragma unroll
    for (int i = 0; i < 4; i++) {
        int e = t + i * 256;
        int r = e >> 5, c = e & 31;
        tile[r][c] = W[(size_t)(k0 + r) * DL + n0 + c];
    }
    __syncthreads();
    #pragma unroll
    for (int i = 0; i < 2; i++) {
        int n = (t >> 4) + i * 16;
        int j = t & 15;
        __half2 hp;
        hp.x = __float2half_rn(tile[2 * j][n]);
        hp.y = __float2half_rn(tile[2 * j + 1][n]);
        *(__half2*)(g_B + (size_t)(n0 + n) * KC + k0 + 2 * j) = hp;
    }
}

// ---------------------------------------------------------------------------
// 4. mma.sync GEMM: D[2048,4096] = A[2048,768] @ B[4096,768]^T + bias
//    128x128 tile/CTA, 8 warps x (64x32), KCHUNK=64, SW128 smem,
//    3-stage cp.async pipeline, 2 CTAs/SM, CTA-swizzled for L2 locality.
// ---------------------------------------------------------------------------
#define STAGE_BYTES 32768
#define SA_OFF(st) ((st) * STAGE_BYTES)
#define SB_OFF(st) ((st) * STAGE_BYTES + 16384)
#define SMEM_TOTAL (3 * STAGE_BYTES)    // 96 KB

__global__ void __launch_bounds__(256, 2)
gemm_mma_kernel(const float* __restrict__ bias, float* __restrict__ out) {
    extern __shared__ __align__(1024) char smem[];
    uint32_t sbase = smem_u32(smem);
    int tid = threadIdx.x;
    int wid = tid >> 5, lane = tid & 31;
    // swizzle: mblk inner -> 296 concurrent CTAs share all of A + ~18 B tiles
    int mblk = blockIdx.x & 15;          // 16
    int nblk = blockIdx.x >> 4;          // 32
    int m0 = mblk * TM, n0 = nblk * TN;
    int wm = (wid & 1) * 64;             // warp M offset
    int wn = (wid >> 1) * 32;            // warp N offset

    const __half* Abase = g_A + (size_t)m0 * KC;
    const __half* Bbase = g_B + (size_t)n0 * KC;

    // ldmatrix lane addressing
    int q = lane >> 3, r8 = lane & 7;
    int qm = (q & 1) * 8;
    int qk = (q >> 1) * 16;

    float acc[4][4][4];
    #pragma unroll
    for (int a = 0; a < 4; a++)
        #pragma unroll
        for (int b = 0; b < 4; b++)
            #pragma unroll
            for (int c = 0; c < 4; c++) acc[a][b][c] = 0.f;

    #define ISSUE(cc) do { \
        int _stg = (cc) % 3; \
        const __half* Ap = Abase + (size_t)(cc) * KCHUNK; \
        const __half* Bp = Bbase + (size_t)(cc) * KCHUNK; \
        _Pragma("unroll") \
        for (int i = 0; i < 4; i++) { \
            int f = tid + i * 256; \
            int row = f >> 3, j = f & 7; \
            int off = SW128(row * 128 + j * 16); \
            cp16(sbase + SA_OFF(_stg) + off, Ap + (size_t)row * KC + j * 8); \
            cp16(sbase + SB_OFF(_stg) + off, Bp + (size_t)row * KC + j * 8); \
        } \
    } while (0)

    ISSUE(0); CP_COMMIT();
    ISSUE(1); CP_COMMIT();

    #pragma unroll 1
    for (int c = 0; c < NCHUNK; c++) {
        if (c + 2 < NCHUNK) ISSUE(c + 2);
        CP_COMMIT();
        CP_WAIT2();                      // stage c's group complete
        __syncthreads();

        int st = c % 3;
        uint32_t abuf = sbase + SA_OFF(st);
        uint32_t bbuf = sbase + SB_OFF(st);
        #pragma unroll
        for (int ks = 0; ks < 4; ks++) {
            uint32_t afr[4][4], bfr[2][4];
            #pragma unroll
            for (int mt = 0; mt < 4; mt++)
                ldsm4(afr[mt], abuf + SW128((wm + mt * 16 + qm + r8) * 128 + ks * 32 + qk));
            #pragma unroll
            for (int nt = 0; nt < 2; nt++)
                ldsm4(bfr[nt], bbuf + SW128((wn + nt * 16 + qm + r8) * 128 + ks * 32 + qk));
            #pragma unroll
            for (int mt = 0; mt < 4; mt++)
                #pragma unroll
                for (int nf = 0; nf < 4; nf++) {
                    int nt = nf >> 1, half = nf & 1;
                    mma_f16(acc[mt][nf], afr[mt], bfr[nt][half], bfr[nt][half + 2]);
                }
        }
        __syncthreads();                 // all reads of buf st done
    }

    // epilogue: C frag m16n8: c0,c1=(row g, col 2i,2i+1); c2,c3=(row g+8)
    int g = lane >> 2, i2 = (lane & 3) * 2;
    #pragma unroll
    for (int mt = 0; mt < 4; mt++) {
        #pragma unroll
        for (int rh = 0; rh < 2; rh++) {
            int m = m0 + wm + mt * 16 + rh * 8 + g;
            int b = m >> 5, kk = m & 31;
            float* orow = out + (size_t)(b * OUT_S + kk) * DL + n0 + wn;
            #pragma unroll
            for (int nf = 0; nf < 4; nf++) {
                int n = nf * 8 + i2;
                float2 bb = *(const float2*)(bias + n0 + wn + n);
                float2 o;
                o.x = acc[mt][nf][rh * 2 + 0] + bb.x;
                o.y = acc[mt][nf][rh * 2 + 1] + bb.y;
                *(float2*)(orow + n) = o;
            }
        }
    }
}

// ---------------------------------------------------------------------------
// 5a-5d. Counting sort of rows by id -> g_perm (ascending id order).
//    Duplicate ids land adjacent => gather's second read L2-hits, and the
//    table read stream becomes quasi-sequential. Within-id order is
//    nondeterministic (atomics) but harmless: identical source bytes.
// ---------------------------------------------------------------------------
__global__ void __launch_bounds__(256)
hist_zero_kernel() {
    int i = blockIdx.x * 256 + threadIdx.x;
    if (i < VOCAB) g_hist[i] = 0;
}
__global__ void __launch_bounds__(256)
hist_count_kernel(const int* __restrict__ ids32) {
    int is64 = sniff_is64(ids32);
    int r = blockIdx.x * 256 + threadIdx.x;
    if (r < NROWS) atomicAdd(&g_hist[(int)load_id(ids32, r, is64)], 1);
}
__global__ void __launch_bounds__(1024)
hist_scan_kernel() {
    __shared__ int ssum[1024];
    int t = threadIdx.x;
    int cnt[32];
    int base = t * 32;
    int local = 0;
    #pragma unroll
    for (int i = 0; i < 32; i++) {
        int idx = base + i;
        cnt[i] = (idx < VOCAB) ? g_hist[idx] : 0;
        local += cnt[i];
    }
    ssum[t] = local;
    __syncthreads();
    // Kogge-Stone inclusive scan over 1024 partials
    for (int st = 1; st < 1024; st <<= 1) {
        int v = (t >= st) ? ssum[t - st] : 0;
        __syncthreads();
        ssum[t] += v;
        __syncthreads();
    }
    int run = (t > 0) ? ssum[t - 1] : 0;   // exclusive prefix of this chunk
    #pragma unroll
    for (int i = 0; i < 32; i++) {
        int idx = base + i;
        if (idx < VOCAB) g_hist[idx] = run;
        run += cnt[i];
    }
}
__global__ void __launch_bounds__(256)
scatter_kernel(const int* __restrict__ ids32) {
    int is64 = sniff_is64(ids32);
    int r = blockIdx.x * 256 + threadIdx.x;
    if (r < NROWS) {
        int pos = atomicAdd(&g_hist[(int)load_id(ids32, r, is64)], 1);
        g_perm[pos] = r;
    }
}

// ---------------------------------------------------------------------------
// 5e. Embedding gather in id-sorted order: persistent grid-stride,
//     4 rows/iter, cached reads (adjacent duplicates hit L2), streaming
//     stores.
// ---------------------------------------------------------------------------
#define GATHER_BLOCKS 1184   // 148 SMs x 8 resident blocks
__global__ void __launch_bounds__(256)
gather_kernel(const int* __restrict__ ids32,
              const float* __restrict__ table,
              float* __restrict__ out) {
    __shared__ int s_is64;
    int tid = threadIdx.x;
    if (tid < 32) {
        int v = sniff_is64(ids32);
        if (tid == 0) s_is64 = v;
    }
    __syncthreads();
    int is64 = s_is64;

    for (int i0 = blockIdx.x * 4; i0 < NROWS; i0 += GATHER_BLOCKS * 4) {
        const float4* src[4];
        float4* dst[4];
        #pragma unroll
        for (int k = 0; k < 4; k++) {
            int r = g_perm[i0 + k];
            long long id = load_id(ids32, r, is64);
            src[k] = (const float4*)(table + (size_t)id * DL);
            dst[k] = (float4*)(out + (size_t)((r >> 9) * OUT_S + TOPK + (r & 511)) * DL);
        }
        float4 v[4][4];
        #pragma unroll
        for (int k = 0; k < 4; k++)
            #pragma unroll
            for (int i = 0; i < 4; i++)
                v[k][i] = src[k][tid + i * 256];
        #pragma unroll
        for (int k = 0; k < 4; k++)
            #pragma unroll
            for (int i = 0; i < 4; i++)
                __stcs(dst[k] + tid + i * 256, v[k][i]);
    }
}

// ---------------------------------------------------------------------------
// kernel_launch: fork immediately; s2 = sort chain -> gather, s3 = convertB,
// main = scores -> topk -> convA -> (wait convertB) -> cp.async mma GEMM.
// metadata order: vision_tokens, input_ids, ln_gamma, ln_beta, scorer_w,
//                 scorer_b, proj_w, proj_b, embed_table
// ---------------------------------------------------------------------------
extern "C" void kernel_launch(void* const* d_in, const int* in_sizes, int n_in,
                              void* d_out, int out_size) {
    const float* vision_tokens = (const float*)d_in[0];
    const void*  input_ids     = d_in[1];
    const float* ln_gamma      = (const float*)d_in[2];
    const float* scorer_w      = (const float*)d_in[4];
    const float* proj_w        = (const float*)d_in[6];
    const float* proj_b        = (const float*)d_in[7];
    const float* embed_table   = (const float*)d_in[8];
    float* out = (float*)d_out;

    static cudaStream_t s2 = nullptr, s3 = nullptr;
    static cudaEvent_t eFork = nullptr, eB = nullptr, eG = nullptr;
    if (s2 == nullptr) {
        cudaStreamCreateWithFlags(&s2, cudaStreamNonBlocking);
        cudaStreamCreateWithFlags(&s3, cudaStreamNonBlocking);
        cudaEventCreateWithFlags(&eFork, cudaEventDisableTiming);
        cudaEventCreateWithFlags(&eB, cudaEventDisableTiming);
        cudaEventCreateWithFlags(&eG, cudaEventDisableTiming);
        cudaFuncSetAttribute(gemm_mma_kernel,
                             cudaFuncAttributeMaxDynamicSharedMemorySize, SMEM_TOTAL);
    }

    cudaEventRecord(eFork, 0);
    cudaStreamWaitEvent(s2, eFork, 0);
    cudaStreamWaitEvent(s3, eFork, 0);

    // stream s2: counting sort by id, then the DRAM-bound gather
    const int* ids32 = (const int*)input_ids;
    hist_zero_kernel<<<(VOCAB + 255) / 256, 256, 0, s2>>>();
    hist_count_kernel<<<(NROWS + 255) / 256, 256, 0, s2>>>(ids32);
    hist_scan_kernel<<<1, 1024, 0, s2>>>();
    scatter_kernel<<<(NROWS + 255) / 256, 256, 0, s2>>>(ids32);
    gather_kernel<<<GATHER_BLOCKS, 256, 0, s2>>>(ids32, embed_table, out);
    cudaEventRecord(eG, s2);

    // stream s3: B conversion for the GEMM
    {
        dim3 gb(DL / 32, DV / 32);    // 128 x 24
        convertB_kernel<<<gb, 256, 0, s3>>>(proj_w);
    }
    cudaEventRecord(eB, s3);

    // main stream: scoring chain -> GEMM
    scores_kernel<<<(B_SZ * P_SZ * 32 + 255) / 256, 256>>>(vision_tokens, ln_gamma, scorer_w);
    topk_kernel<<<(B_SZ * 32 + 255) / 256, 256>>>();
    convertA_kernel<<<M_TOT, 128>>>(vision_tokens);
    cudaStreamWaitEvent(0, eB, 0);
    gemm_mma_kernel<<<(M_TOT / TM) * (DL / TN), 256, SMEM_TOTAL>>>(proj_b, out);

    cudaStreamWaitEvent(0, eG, 0);
}

// round 15
// speedup vs baseline: 1.0253x; 1.0194x over previous
#include <cuda_runtime.h>
#include <cuda_fp16.h>
#include <float.h>
#include <stdint.h>

// ---------------------------------------------------------------------------
// Problem constants (fixed shapes for SparseVLMModel_59725815218738)
// ---------------------------------------------------------------------------
#define B_SZ    64
#define S_SZ    197
#define P_SZ    196
#define T_SZ    512
#define DV      768
#define DL      4096
#define TOPK    32
#define OUT_S   (TOPK + T_SZ)   // 544
#define LN_EPS  1e-5f
#define VOCAB   32000
#define NROWS   (B_SZ * T_SZ)   // 32768

#define M_TOT   (B_SZ * TOPK)   // 2048
#define KC      DV              // 768: plain fp16 GEMM (A,B rounded to fp16)
#define TM      128
#define TN      128
#define KCHUNK  64
#define NCHUNK  (KC / KCHUNK)   // 12

// Scratch (no cudaMalloc allowed)
__device__ float g_scores[B_SZ * P_SZ];
__device__ int   g_topk[M_TOT];
__device__ int   g_hist[VOCAB];
__device__ int   g_perm[NROWS];   // packed (id<<15) | row
__device__ __align__(128) __half g_A[(size_t)M_TOT * KC]; // 3.1 MB
__device__ __align__(128) __half g_B[(size_t)DL * KC];    // 6.3 MB

__device__ __forceinline__ uint32_t smem_u32(const void* p) {
    uint32_t a;
    asm("{ .reg .u64 t; cvta.to.shared.u64 t, %1; cvt.u32.u64 %0, t; }" : "=r"(a) : "l"(p));
    return a;
}
__device__ __forceinline__ void ldsm4(uint32_t* r, uint32_t addr) {
    asm volatile("ldmatrix.sync.aligned.m8n8.x4.shared.b16 {%0,%1,%2,%3}, [%4];"
                 : "=r"(r[0]), "=r"(r[1]), "=r"(r[2]), "=r"(r[3]) : "r"(addr));
}
__device__ __forceinline__ void mma_f16(float* c, const uint32_t* a,
                                        uint32_t b0, uint32_t b1) {
    asm volatile(
        "mma.sync.aligned.m16n8k16.row.col.f32.f16.f16.f32 "
        "{%0,%1,%2,%3}, {%4,%5,%6,%7}, {%8,%9}, {%0,%1,%2,%3};"
        : "+f"(c[0]), "+f"(c[1]), "+f"(c[2]), "+f"(c[3])
        : "r"(a[0]), "r"(a[1]), "r"(a[2]), "r"(a[3]), "r"(b0), "r"(b1));
}
__device__ __forceinline__ void cp16(uint32_t saddr, const void* g) {
    asm volatile("cp.async.cg.shared.global [%0], [%1], 16;"
                 :: "r"(saddr), "l"(g) : "memory");
}
#define CP_COMMIT() asm volatile("cp.async.commit_group;" ::: "memory")
#define CP_WAIT2()  asm volatile("cp.async.wait_group 2;" ::: "memory")
#define SW128(x) ((x) ^ (((x) >> 3) & 0x70))

// Per-block int64/int32 sniff: ids < 32000, so int64 => all odd words zero.
__device__ __forceinline__ int sniff_is64(const int* __restrict__ ids32) {
    unsigned nz = __ballot_sync(0xffffffffu,
                                ids32[2 * (threadIdx.x & 31) + 1] != 0);
    return (nz == 0u) ? 1 : 0;
}
__device__ __forceinline__ long long load_id(const int* __restrict__ ids32,
                                             int r, int is64) {
    return is64 ? ((const long long*)ids32)[r] : (long long)ids32[r];
}

// ---------------------------------------------------------------------------
// 1. Scores: warp-per-row LayerNorm dot (ordering-equivalent form)
// ---------------------------------------------------------------------------
__global__ void __launch_bounds__(256)
scores_kernel(const float* __restrict__ vt,
              const float* __restrict__ gamma,
              const float* __restrict__ w) {
    int warp = (blockIdx.x * 256 + threadIdx.x) >> 5;
    int lane = threadIdx.x & 31;
    if (warp >= B_SZ * P_SZ) return;
    int b = warp / P_SZ, s = warp % P_SZ;
    const float4* x4 = (const float4*)(vt + (size_t)(b * S_SZ + 1 + s) * DV);
    const float4* g4 = (const float4*)gamma;
    const float4* w4 = (const float4*)w;

    float s1 = 0.f, s2 = 0.f, sgw = 0.f, cgw = 0.f;
    #pragma unroll
    for (int i = 0; i < 6; i++) {
        int idx = lane + i * 32;
        float4 xv = x4[idx];
        float4 gv = g4[idx];
        float4 wv = w4[idx];
        float gw0 = gv.x * wv.x, gw1 = gv.y * wv.y, gw2 = gv.z * wv.z, gw3 = gv.w * wv.w;
        s1 += xv.x + xv.y + xv.z + xv.w;
        s2 += xv.x * xv.x + xv.y * xv.y + xv.z * xv.z + xv.w * xv.w;
        sgw += xv.x * gw0 + xv.y * gw1 + xv.z * gw2 + xv.w * gw3;
        cgw += gw0 + gw1 + gw2 + gw3;
    }
    #pragma unroll
    for (int st = 16; st > 0; st >>= 1) {
        s1  += __shfl_xor_sync(0xffffffffu, s1, st);
        s2  += __shfl_xor_sync(0xffffffffu, s2, st);
        sgw += __shfl_xor_sync(0xffffffffu, sgw, st);
        cgw += __shfl_xor_sync(0xffffffffu, cgw, st);
    }
    if (lane == 0) {
        float mean = s1 * (1.0f / DV);
        float var  = s2 * (1.0f / DV) - mean * mean;
        float rstd = rsqrtf(var + LN_EPS);
        g_scores[warp] = rstd * (sgw - mean * cgw);
    }
}

// ---------------------------------------------------------------------------
// 2. Top-32 per batch: warp-per-batch register argmax, stable ties.
// ---------------------------------------------------------------------------
__global__ void __launch_bounds__(256)
topk_kernel() {
    int warp = (blockIdx.x * 256 + threadIdx.x) >> 5;   // 0..63
    int lane = threadIdx.x & 31;
    if (warp >= B_SZ) return;
    float v[7];
    #pragma unroll
    for (int i = 0; i < 7; i++) {
        int idx = lane + i * 32;
        v[i] = (idx < P_SZ) ? g_scores[warp * P_SZ + idx] : -FLT_MAX;
    }
    for (int k = 0; k < TOPK; k++) {
        float best = -FLT_MAX; int bi = 0;
        #pragma unroll
        for (int i = 0; i < 7; i++)
            if (v[i] > best) { best = v[i]; bi = i; }    // ascending idx: stable
        int bidx = lane + bi * 32;
        #pragma unroll
        for (int st = 16; st > 0; st >>= 1) {
            float ov = __shfl_xor_sync(0xffffffffu, best, st);
            int   oi = __shfl_xor_sync(0xffffffffu, bidx, st);
            if (ov > best || (ov == best && oi < bidx)) { best = ov; bidx = oi; }
        }
        if (lane == 0) g_topk[warp * TOPK + k] = bidx;
        if ((bidx & 31) == lane) v[bidx >> 5] = -FLT_MAX;
    }
}

// ---------------------------------------------------------------------------
// 3a. Convert gathered A rows fp32 -> fp16 (single term, K = 768)
// ---------------------------------------------------------------------------
__global__ void __launch_bounds__(128)
convertA_kernel(const float* __restrict__ vt) {
    int m = blockIdx.x;                // 0..2047
    int b = m >> 5;
    size_t base = (size_t)(b * S_SZ + 1 + g_topk[m]) * DV;
    __half* rowA = g_A + (size_t)m * KC;
    int t = threadIdx.x;
    #pragma unroll
    for (int i = 0; i < 3; i++) {
        int p = t + i * 128;           // pair 0..383
        float v0 = vt[base + 2 * p], v1 = vt[base + 2 * p + 1];
        __half2 hp;
        hp.x = __float2half_rn(v0);
        hp.y = __float2half_rn(v1);
        *(__half2*)(rowA + 2 * p) = hp;
    }
}

// ---------------------------------------------------------------------------
// 3b. Convert+transpose proj_w [768,4096] -> g_B [4096][768] fp16
// ---------------------------------------------------------------------------
__global__ void __launch_bounds__(256)
convertB_kernel(const float* __restrict__ W) {
    __shared__ float tile[32][33];
    int n0 = blockIdx.x * 32;          // 128 blocks
    int k0 = blockIdx.y * 32;          // 24 blocks
    int t = threadIdx.x;
    #pragma unroll
    for (int i = 0; i < 4; i++) {
        int e = t + i * 256;
        int r = e >> 5, c = e & 31;
        tile[r][c] = W[(size_t)(k0 + r) * DL + n0 + c];
    }
    __syncthreads();
    #pragma unroll
    for (int i = 0; i < 2; i++) {
        int n = (t >> 4) + i * 16;
        int j = t & 15;
        __half2 hp;
        hp.x = __float2half_rn(tile[2 * j][n]);
        hp.y = __float2half_rn(tile[2 * j + 1][n]);
        *(__half2*)(g_B + (size_t)(n0 + n) * KC + k0 + 2 * j) = hp;
    }
}

// ---------------------------------------------------------------------------
// 4. mma.sync GEMM: D[2048,4096] = A[2048,768] @ B[4096,768]^T + bias
//    128x128 tile/CTA, 8 warps x (64x32), KCHUNK=64, SW128 smem,
//    3-stage cp.async pipeline, 2 CTAs/SM, CTA-swizzled for L2 locality.
// ---------------------------------------------------------------------------
#define STAGE_BYTES 32768
#define SA_OFF(st) ((st) * STAGE_BYTES)
#define SB_OFF(st) ((st) * STAGE_BYTES + 16384)
#define SMEM_TOTAL (3 * STAGE_BYTES)    // 96 KB

__global__ void __launch_bounds__(256, 2)
gemm_mma_kernel(const float* __restrict__ bias, float* __restrict__ out) {
    extern __shared__ __align__(1024) char smem[];
    uint32_t sbase = smem_u32(smem);
    int tid = threadIdx.x;
    int wid = tid >> 5, lane = tid & 31;
    // swizzle: mblk inner -> 296 concurrent CTAs share all of A + ~18 B tiles
    int mblk = blockIdx.x & 15;          // 16
    int nblk = blockIdx.x >> 4;          // 32
    int m0 = mblk * TM, n0 = nblk * TN;
    int wm = (wid & 1) * 64;             // warp M offset
    int wn = (wid >> 1) * 32;            // warp N offset

    const __half* Abase = g_A + (size_t)m0 * KC;
    const __half* Bbase = g_B + (size_t)n0 * KC;

    // ldmatrix lane addressing
    int q = lane >> 3, r8 = lane & 7;
    int qm = (q & 1) * 8;
    int qk = (q >> 1) * 16;

    float acc[4][4][4];
    #pragma unroll
    for (int a = 0; a < 4; a++)
        #pragma unroll
        for (int b = 0; b < 4; b++)
            #pragma unroll
            for (int c = 0; c < 4; c++) acc[a][b][c] = 0.f;

    #define ISSUE(cc) do { \
        int _stg = (cc) % 3; \
        const __half* Ap = Abase + (size_t)(cc) * KCHUNK; \
        const __half* Bp = Bbase + (size_t)(cc) * KCHUNK; \
        _Pragma("unroll") \
        for (int i = 0; i < 4; i++) { \
            int f = tid + i * 256; \
            int row = f >> 3, j = f & 7; \
            int off = SW128(row * 128 + j * 16); \
            cp16(sbase + SA_OFF(_stg) + off, Ap + (size_t)row * KC + j * 8); \
            cp16(sbase + SB_OFF(_stg) + off, Bp + (size_t)row * KC + j * 8); \
        } \
    } while (0)

    ISSUE(0); CP_COMMIT();
    ISSUE(1); CP_COMMIT();

    #pragma unroll 1
    for (int c = 0; c < NCHUNK; c++) {
        if (c + 2 < NCHUNK) ISSUE(c + 2);
        CP_COMMIT();
        CP_WAIT2();                      // stage c's group complete
        __syncthreads();

        int st = c % 3;
        uint32_t abuf = sbase + SA_OFF(st);
        uint32_t bbuf = sbase + SB_OFF(st);
        #pragma unroll
        for (int ks = 0; ks < 4; ks++) {
            uint32_t afr[4][4], bfr[2][4];
            #pragma unroll
            for (int mt = 0; mt < 4; mt++)
                ldsm4(afr[mt], abuf + SW128((wm + mt * 16 + qm + r8) * 128 + ks * 32 + qk));
            #pragma unroll
            for (int nt = 0; nt < 2; nt++)
                ldsm4(bfr[nt], bbuf + SW128((wn + nt * 16 + qm + r8) * 128 + ks * 32 + qk));
            #pragma unroll
            for (int mt = 0; mt < 4; mt++)
                #pragma unroll
                for (int nf = 0; nf < 4; nf++) {
                    int nt = nf >> 1, half = nf & 1;
                    mma_f16(acc[mt][nf], afr[mt], bfr[nt][half], bfr[nt][half + 2]);
                }
        }
        __syncthreads();                 // all reads of buf st done
    }

    // epilogue: C frag m16n8: c0,c1=(row g, col 2i,2i+1); c2,c3=(row g+8)
    int g = lane >> 2, i2 = (lane & 3) * 2;
    #pragma unroll
    for (int mt = 0; mt < 4; mt++) {
        #pragma unroll
        for (int rh = 0; rh < 2; rh++) {
            int m = m0 + wm + mt * 16 + rh * 8 + g;
            int b = m >> 5, kk = m & 31;
            float* orow = out + (size_t)(b * OUT_S + kk) * DL + n0 + wn;
            #pragma unroll
            for (int nf = 0; nf < 4; nf++) {
                int n = nf * 8 + i2;
                float2 bb = *(const float2*)(bias + n0 + wn + n);
                float2 o;
                o.x = acc[mt][nf][rh * 2 + 0] + bb.x;
                o.y = acc[mt][nf][rh * 2 + 1] + bb.y;
                *(float2*)(orow + n) = o;
            }
        }
    }
}

// ---------------------------------------------------------------------------
// 5a-5d. Counting sort of rows by id -> g_perm, packed (id<<15)|row.
//    Duplicate ids land adjacent => gather's repeat reads L2-hit, and the
//    table read stream becomes quasi-sequential. Within-id order is
//    nondeterministic (atomics) but harmless: identical id => identical bytes.
// ---------------------------------------------------------------------------
__global__ void __launch_bounds__(256)
hist_zero_kernel() {
    int i = blockIdx.x * 256 + threadIdx.x;
    if (i < VOCAB) g_hist[i] = 0;
}
__global__ void __launch_bounds__(256)
hist_count_kernel(const int* __restrict__ ids32) {
    int is64 = sniff_is64(ids32);
    int r = blockIdx.x * 256 + threadIdx.x;
    if (r < NROWS) atomicAdd(&g_hist[(int)load_id(ids32, r, is64)], 1);
}
__global__ void __launch_bounds__(1024)
hist_scan_kernel() {
    __shared__ int ssum[1024];
    int t = threadIdx.x;
    int cnt[32];
    int base = t * 32;
    int local = 0;
    #pragma unroll
    for (int i = 0; i < 32; i++) {
        int idx = base + i;
        cnt[i] = (idx < VOCAB) ? g_hist[idx] : 0;
        local += cnt[i];
    }
    ssum[t] = local;
    __syncthreads();
    // Kogge-Stone inclusive scan over 1024 partials
    for (int st = 1; st < 1024; st <<= 1) {
        int v = (t >= st) ? ssum[t - st] : 0;
        __syncthreads();
        ssum[t] += v;
        __syncthreads();
    }
    int run = (t > 0) ? ssum[t - 1] : 0;   // exclusive prefix of this chunk
    #pragma unroll
    for (int i = 0; i < 32; i++) {
        int idx = base + i;
        if (idx < VOCAB) g_hist[idx] = run;
        run += cnt[i];
    }
}
__global__ void __launch_bounds__(256)
scatter_kernel(const int* __restrict__ ids32) {
    int is64 = sniff_is64(ids32);
    int r = blockIdx.x * 256 + threadIdx.x;
    if (r < NROWS) {
        int id = (int)load_id(ids32, r, is64);
        int pos = atomicAdd(&g_hist[id], 1);
        g_perm[pos] = (id << 15) | r;      // id < 2^15, r < 2^15
    }
}

// ---------------------------------------------------------------------------
// 5e. Embedding gather in id-sorted order: persistent grid-stride,
//     software-pipelined 2 rows/stage (next stage's loads issue before the
//     current stage's stores -> the DRAM read stream never drains).
//     Cached reads (adjacent duplicates hit L2), streaming stores.
// ---------------------------------------------------------------------------
#define GATHER_BLOCKS 1184   // 148 SMs x 8 launch slots (3 resident by regs)
__global__ void __launch_bounds__(256)
gather_kernel(const float* __restrict__ table, float* __restrict__ out) {
    int tid = threadIdx.x;
    const int STR = GATHER_BLOCKS * 2;
    int i = blockIdx.x * 2;              // always < NROWS (2366 < 32768)

    const float4 *s0, *s1;
    float4 *d0, *d1;
    float4 v[2][4];

    // prologue: pointers + first loads
    {
        int p0 = g_perm[i], p1 = g_perm[i + 1];
        s0 = (const float4*)(table + (size_t)(p0 >> 15) * DL);
        s1 = (const float4*)(table + (size_t)(p1 >> 15) * DL);
        int r0 = p0 & 32767, r1 = p1 & 32767;
        d0 = (float4*)(out + (size_t)((r0 >> 9) * OUT_S + TOPK + (r0 & 511)) * DL);
        d1 = (float4*)(out + (size_t)((r1 >> 9) * OUT_S + TOPK + (r1 & 511)) * DL);
        #pragma unroll
        for (int j = 0; j < 4; j++) {
            v[0][j] = s0[tid + j * 256];
            v[1][j] = s1[tid + j * 256];
        }
    }

    #pragma unroll 1
    while (true) {
        int nx = i + STR;
        bool has = (nx < NROWS);
        const float4 *ns0 = s0, *ns1 = s1;
        float4 *nd0 = d0, *nd1 = d1;
        float4 w[2][4];
        if (has) {
            int p0 = g_perm[nx], p1 = g_perm[nx + 1];
            ns0 = (const float4*)(table + (size_t)(p0 >> 15) * DL);
            ns1 = (const float4*)(table + (size_t)(p1 >> 15) * DL);
            int r0 = p0 & 32767, r1 = p1 & 32767;
            nd0 = (float4*)(out + (size_t)((r0 >> 9) * OUT_S + TOPK + (r0 & 511)) * DL);
            nd1 = (float4*)(out + (size_t)((r1 >> 9) * OUT_S + TOPK + (r1 & 511)) * DL);
            #pragma unroll
            for (int j = 0; j < 4; j++) {       // issue next loads FIRST
                w[0][j] = ns0[tid + j * 256];
                w[1][j] = ns1[tid + j * 256];
            }
        }
        // store current stage while next loads are in flight
        #pragma unroll
        for (int j = 0; j < 4; j++) {
            __stcs(d0 + tid + j * 256, v[0][j]);
            __stcs(d1 + tid + j * 256, v[1][j]);
        }
        if (!has) break;
        #pragma unroll
        for (int j = 0; j < 4; j++) { v[0][j] = w[0][j]; v[1][j] = w[1][j]; }
        s0 = ns0; s1 = ns1; d0 = nd0; d1 = nd1;
        i = nx;
    }
}

// ---------------------------------------------------------------------------
// kernel_launch: fork immediately; s2 = sort chain -> gather, s3 = convertB,
// main = scores -> topk -> convA -> (wait convertB) -> cp.async mma GEMM.
// metadata order: vision_tokens, input_ids, ln_gamma, ln_beta, scorer_w,
//                 scorer_b, proj_w, proj_b, embed_table
// ---------------------------------------------------------------------------
extern "C" void kernel_launch(void* const* d_in, const int* in_sizes, int n_in,
                              void* d_out, int out_size) {
    const float* vision_tokens = (const float*)d_in[0];
    const void*  input_ids     = d_in[1];
    const float* ln_gamma      = (const float*)d_in[2];
    const float* scorer_w      = (const float*)d_in[4];
    const float* proj_w        = (const float*)d_in[6];
    const float* proj_b        = (const float*)d_in[7];
    const float* embed_table   = (const float*)d_in[8];
    float* out = (float*)d_out;

    static cudaStream_t s2 = nullptr, s3 = nullptr;
    static cudaEvent_t eFork = nullptr, eB = nullptr, eG = nullptr;
    if (s2 == nullptr) {
        cudaStreamCreateWithFlags(&s2, cudaStreamNonBlocking);
        cudaStreamCreateWithFlags(&s3, cudaStreamNonBlocking);
        cudaEventCreateWithFlags(&eFork, cudaEventDisableTiming);
        cudaEventCreateWithFlags(&eB, cudaEventDisableTiming);
        cudaEventCreateWithFlags(&eG, cudaEventDisableTiming);
        cudaFuncSetAttribute(gemm_mma_kernel,
                             cudaFuncAttributeMaxDynamicSharedMemorySize, SMEM_TOTAL);
    }

    cudaEventRecord(eFork, 0);
    cudaStreamWaitEvent(s2, eFork, 0);
    cudaStreamWaitEvent(s3, eFork, 0);

    // stream s2: counting sort by id, then the DRAM-bound gather
    const int* ids32 = (const int*)input_ids;
    hist_zero_kernel<<<(VOCAB + 255) / 256, 256, 0, s2>>>();
    hist_count_kernel<<<(NROWS + 255) / 256, 256, 0, s2>>>(ids32);
    hist_scan_kernel<<<1, 1024, 0, s2>>>();
    scatter_kernel<<<(NROWS + 255) / 256, 256, 0, s2>>>(ids32);
    gather_kernel<<<GATHER_BLOCKS, 256, 0, s2>>>(embed_table, out);
    cudaEventRecord(eG, s2);

    // stream s3: B conversion for the GEMM
    {
        dim3 gb(DL / 32, DV / 32);    // 128 x 24
        convertB_kernel<<<gb, 256, 0, s3>>>(proj_w);
    }
    cudaEventRecord(eB, s3);

    // main stream: scoring chain -> GEMM
    scores_kernel<<<(B_SZ * P_SZ * 32 + 255) / 256, 256>>>(vision_tokens, ln_gamma, scorer_w);
    topk_kernel<<<(B_SZ * 32 + 255) / 256, 256>>>();
    convertA_kernel<<<M_TOT, 128>>>(vision_tokens);
    cudaStreamWaitEvent(0, eB, 0);
    gemm_mma_kernel<<<(M_TOT / TM) * (DL / TN), 256, SMEM_TOTAL>>>(proj_b, out);

    cudaStreamWaitEvent(0, eG, 0);
}

// round 16
// speedup vs baseline: 1.0360x; 1.0104x over previous
#include <cuda_runtime.h>
#include <cuda_fp16.h>
#include <float.h>
#include <stdint.h>

// ---------------------------------------------------------------------------
// Problem constants (fixed shapes for SparseVLMModel_59725815218738)
// ---------------------------------------------------------------------------
#define B_SZ    64
#define S_SZ    197
#define P_SZ    196
#define T_SZ    512
#define DV      768
#define DL      4096
#define TOPK    32
#define OUT_S   (TOPK + T_SZ)   // 544
#define LN_EPS  1e-5f
#define VOCAB   32000
#define NROWS   (B_SZ * T_SZ)   // 32768

#define M_TOT   (B_SZ * TOPK)   // 2048
#define KC      DV              // 768: plain fp16 GEMM (A,B rounded to fp16)
#define TM      128
#define TN      128
#define KCHUNK  64
#define NCHUNK  (KC / KCHUNK)   // 12

// Scratch (no cudaMalloc allowed)
__device__ float g_scores[B_SZ * P_SZ];
__device__ int   g_topk[M_TOT];
__device__ int   g_perm[NROWS];   // packed (id<<15) | row
__device__ __align__(128) __half g_A[(size_t)M_TOT * KC]; // 3.1 MB
__device__ __align__(128) __half g_B[(size_t)DL * KC];    // 6.3 MB

__device__ __forceinline__ uint32_t smem_u32(const void* p) {
    uint32_t a;
    asm("{ .reg .u64 t; cvta.to.shared.u64 t, %1; cvt.u32.u64 %0, t; }" : "=r"(a) : "l"(p));
    return a;
}
__device__ __forceinline__ void ldsm4(uint32_t* r, uint32_t addr) {
    asm volatile("ldmatrix.sync.aligned.m8n8.x4.shared.b16 {%0,%1,%2,%3}, [%4];"
                 : "=r"(r[0]), "=r"(r[1]), "=r"(r[2]), "=r"(r[3]) : "r"(addr));
}
__device__ __forceinline__ void mma_f16(float* c, const uint32_t* a,
                                        uint32_t b0, uint32_t b1) {
    asm volatile(
        "mma.sync.aligned.m16n8k16.row.col.f32.f16.f16.f32 "
        "{%0,%1,%2,%3}, {%4,%5,%6,%7}, {%8,%9}, {%0,%1,%2,%3};"
        : "+f"(c[0]), "+f"(c[1]), "+f"(c[2]), "+f"(c[3])
        : "r"(a[0]), "r"(a[1]), "r"(a[2]), "r"(a[3]), "r"(b0), "r"(b1));
}
__device__ __forceinline__ void cp16(uint32_t saddr, const void* g) {
    asm volatile("cp.async.cg.shared.global [%0], [%1], 16;"
                 :: "r"(saddr), "l"(g) : "memory");
}
#define CP_COMMIT() asm volatile("cp.async.commit_group;" ::: "memory")
#define CP_WAIT2()  asm volatile("cp.async.wait_group 2;" ::: "memory")
#define SW128(x) ((x) ^ (((x) >> 3) & 0x70))

// ---------------------------------------------------------------------------
// 1. Scores: warp-per-row LayerNorm dot (ordering-equivalent form)
// ---------------------------------------------------------------------------
__global__ void __launch_bounds__(256)
scores_kernel(const float* __restrict__ vt,
              const float* __restrict__ gamma,
              const float* __restrict__ w) {
    int warp = (blockIdx.x * 256 + threadIdx.x) >> 5;
    int lane = threadIdx.x & 31;
    if (warp >= B_SZ * P_SZ) return;
    int b = warp / P_SZ, s = warp % P_SZ;
    const float4* x4 = (const float4*)(vt + (size_t)(b * S_SZ + 1 + s) * DV);
    const float4* g4 = (const float4*)gamma;
    const float4* w4 = (const float4*)w;

    float s1 = 0.f, s2 = 0.f, sgw = 0.f, cgw = 0.f;
    #pragma unroll
    for (int i = 0; i < 6; i++) {
        int idx = lane + i * 32;
        float4 xv = x4[idx];
        float4 gv = g4[idx];
        float4 wv = w4[idx];
        float gw0 = gv.x * wv.x, gw1 = gv.y * wv.y, gw2 = gv.z * wv.z, gw3 = gv.w * wv.w;
        s1 += xv.x + xv.y + xv.z + xv.w;
        s2 += xv.x * xv.x + xv.y * xv.y + xv.z * xv.z + xv.w * xv.w;
        sgw += xv.x * gw0 + xv.y * gw1 + xv.z * gw2 + xv.w * gw3;
        cgw += gw0 + gw1 + gw2 + gw3;
    }
    #pragma unroll
    for (int st = 16; st > 0; st >>= 1) {
        s1  += __shfl_xor_sync(0xffffffffu, s1, st);
        s2  += __shfl_xor_sync(0xffffffffu, s2, st);
        sgw += __shfl_xor_sync(0xffffffffu, sgw, st);
        cgw += __shfl_xor_sync(0xffffffffu, cgw, st);
    }
    if (lane == 0) {
        float mean = s1 * (1.0f / DV);
        float var  = s2 * (1.0f / DV) - mean * mean;
        float rstd = rsqrtf(var + LN_EPS);
        g_scores[warp] = rstd * (sgw - mean * cgw);
    }
}

// ---------------------------------------------------------------------------
// 2. Top-32 per batch: warp-per-batch register argmax, stable ties.
// ---------------------------------------------------------------------------
__global__ void __launch_bounds__(256)
topk_kernel() {
    int warp = (blockIdx.x * 256 + threadIdx.x) >> 5;   // 0..63
    int lane = threadIdx.x & 31;
    if (warp >= B_SZ) return;
    float v[7];
    #pragma unroll
    for (int i = 0; i < 7; i++) {
        int idx = lane + i * 32;
        v[i] = (idx < P_SZ) ? g_scores[warp * P_SZ + idx] : -FLT_MAX;
    }
    for (int k = 0; k < TOPK; k++) {
        float best = -FLT_MAX; int bi = 0;
        #pragma unroll
        for (int i = 0; i < 7; i++)
            if (v[i] > best) { best = v[i]; bi = i; }    // ascending idx: stable
        int bidx = lane + bi * 32;
        #pragma unroll
        for (int st = 16; st > 0; st >>= 1) {
            float ov = __shfl_xor_sync(0xffffffffu, best, st);
            int   oi = __shfl_xor_sync(0xffffffffu, bidx, st);
            if (ov > best || (ov == best && oi < bidx)) { best = ov; bidx = oi; }
        }
        if (lane == 0) g_topk[warp * TOPK + k] = bidx;
        if ((bidx & 31) == lane) v[bidx >> 5] = -FLT_MAX;
    }
}

// ---------------------------------------------------------------------------
// 3a. Convert gathered A rows fp32 -> fp16 (single term, K = 768)
// ---------------------------------------------------------------------------
__global__ void __launch_bounds__(128)
convertA_kernel(const float* __restrict__ vt) {
    int m = blockIdx.x;                // 0..2047
    int b = m >> 5;
    size_t base = (size_t)(b * S_SZ + 1 + g_topk[m]) * DV;
    __half* rowA = g_A + (size_t)m * KC;
    int t = threadIdx.x;
    #pragma unroll
    for (int i = 0; i < 3; i++) {
        int p = t + i * 128;           // pair 0..383
        float v0 = vt[base + 2 * p], v1 = vt[base + 2 * p + 1];
        __half2 hp;
        hp.x = __float2half_rn(v0);
        hp.y = __float2half_rn(v1);
        *(__half2*)(rowA + 2 * p) = hp;
    }
}

// ---------------------------------------------------------------------------
// 3b. Convert+transpose proj_w [768,4096] -> g_B [4096][768] fp16
// ---------------------------------------------------------------------------
__global__ void __launch_bounds__(256)
convertB_kernel(const float* __restrict__ W) {
    __shared__ float tile[32][33];
    int n0 = blockIdx.x * 32;          // 128 blocks
    int k0 = blockIdx.y * 32;          // 24 blocks
    int t = threadIdx.x;
    #pragma unroll
    for (int i = 0; i < 4; i++) {
        int e = t + i * 256;
        int r = e >> 5, c = e & 31;
        tile[r][c] = W[(size_t)(k0 + r) * DL + n0 + c];
    }
    __syncthreads();
    #pragma unroll
    for (int i = 0; i < 2; i++) {
        int n = (t >> 4) + i * 16;
        int j = t & 15;
        __half2 hp;
        hp.x = __float2half_rn(tile[2 * j][n]);
        hp.y = __float2half_rn(tile[2 * j + 1][n]);
        *(__half2*)(g_B + (size_t)(n0 + n) * KC + k0 + 2 * j) = hp;
    }
}

// ---------------------------------------------------------------------------
// 4. mma.sync GEMM: D[2048,4096] = A[2048,768] @ B[4096,768]^T + bias
//    128x128 tile/CTA, 8 warps x (64x32), KCHUNK=64, SW128 smem,
//    3-stage cp.async pipeline, 2 CTAs/SM, CTA-swizzled for L2 locality.
// ---------------------------------------------------------------------------
#define STAGE_BYTES 32768
#define SA_OFF(st) ((st) * STAGE_BYTES)
#define SB_OFF(st) ((st) * STAGE_BYTES + 16384)
#define SMEM_TOTAL (3 * STAGE_BYTES)    // 96 KB

__global__ void __launch_bounds__(256, 2)
gemm_mma_kernel(const float* __restrict__ bias, float* __restrict__ out) {
    extern __shared__ __align__(1024) char smem[];
    uint32_t sbase = smem_u32(smem);
    int tid = threadIdx.x;
    int wid = tid >> 5, lane = tid & 31;
    // swizzle: mblk inner -> 296 concurrent CTAs share all of A + ~18 B tiles
    int mblk = blockIdx.x & 15;          // 16
    int nblk = blockIdx.x >> 4;          // 32
    int m0 = mblk * TM, n0 = nblk * TN;
    int wm = (wid & 1) * 64;             // warp M offset
    int wn = (wid >> 1) * 32;            // warp N offset

    const __half* Abase = g_A + (size_t)m0 * KC;
    const __half* Bbase = g_B + (size_t)n0 * KC;

    // ldmatrix lane addressing
    int q = lane >> 3, r8 = lane & 7;
    int qm = (q & 1) * 8;
    int qk = (q >> 1) * 16;

    float acc[4][4][4];
    #pragma unroll
    for (int a = 0; a < 4; a++)
        #pragma unroll
        for (int b = 0; b < 4; b++)
            #pragma unroll
            for (int c = 0; c < 4; c++) acc[a][b][c] = 0.f;

    #define ISSUE(cc) do { \
        int _stg = (cc) % 3; \
        const __half* Ap = Abase + (size_t)(cc) * KCHUNK; \
        const __half* Bp = Bbase + (size_t)(cc) * KCHUNK; \
        _Pragma("unroll") \
        for (int i = 0; i < 4; i++) { \
            int f = tid + i * 256; \
            int row = f >> 3, j = f & 7; \
            int off = SW128(row * 128 + j * 16); \
            cp16(sbase + SA_OFF(_stg) + off, Ap + (size_t)row * KC + j * 8); \
            cp16(sbase + SB_OFF(_stg) + off, Bp + (size_t)row * KC + j * 8); \
        } \
    } while (0)

    ISSUE(0); CP_COMMIT();
    ISSUE(1); CP_COMMIT();

    #pragma unroll 1
    for (int c = 0; c < NCHUNK; c++) {
        if (c + 2 < NCHUNK) ISSUE(c + 2);
        CP_COMMIT();
        CP_WAIT2();                      // stage c's group complete
        __syncthreads();

        int st = c % 3;
        uint32_t abuf = sbase + SA_OFF(st);
        uint32_t bbuf = sbase + SB_OFF(st);
        #pragma unroll
        for (int ks = 0; ks < 4; ks++) {
            uint32_t afr[4][4], bfr[2][4];
            #pragma unroll
            for (int mt = 0; mt < 4; mt++)
                ldsm4(afr[mt], abuf + SW128((wm + mt * 16 + qm + r8) * 128 + ks * 32 + qk));
            #pragma unroll
            for (int nt = 0; nt < 2; nt++)
                ldsm4(bfr[nt], bbuf + SW128((wn + nt * 16 + qm + r8) * 128 + ks * 32 + qk));
            #pragma unroll
            for (int mt = 0; mt < 4; mt++)
                #pragma unroll
                for (int nf = 0; nf < 4; nf++) {
                    int nt = nf >> 1, half = nf & 1;
                    mma_f16(acc[mt][nf], afr[mt], bfr[nt][half], bfr[nt][half + 2]);
                }
        }
        __syncthreads();                 // all reads of buf st done
    }

    // epilogue: C frag m16n8: c0,c1=(row g, col 2i,2i+1); c2,c3=(row g+8)
    int g = lane >> 2, i2 = (lane & 3) * 2;
    #pragma unroll
    for (int mt = 0; mt < 4; mt++) {
        #pragma unroll
        for (int rh = 0; rh < 2; rh++) {
            int m = m0 + wm + mt * 16 + rh * 8 + g;
            int b = m >> 5, kk = m & 31;
            float* orow = out + (size_t)(b * OUT_S + kk) * DL + n0 + wn;
            #pragma unroll
            for (int nf = 0; nf < 4; nf++) {
                int n = nf * 8 + i2;
                float2 bb = *(const float2*)(bias + n0 + wn + n);
                float2 o;
                o.x = acc[mt][nf][rh * 2 + 0] + bb.x;
                o.y = acc[mt][nf][rh * 2 + 1] + bb.y;
                *(float2*)(orow + n) = o;
            }
        }
    }
}

// ---------------------------------------------------------------------------
// 5a. Fused single-block counting sort by id -> g_perm, packed (id<<15)|row.
//     32000-bin histogram lives in shared memory (128 KB); one launch
//     replaces zero/count/scan/scatter (4 launches + global atomics).
//     smem atomics (ATOMS, spread) instead of 318-cyc global atomics.
//     Within-id order nondeterministic but harmless: same id => same bytes.
// ---------------------------------------------------------------------------
#define SORT_THREADS 1024
#define SORT_SMEM ((VOCAB + SORT_THREADS) * 4)   // hist + block-scan partials
__global__ void __launch_bounds__(SORT_THREADS)
sort_kernel(const int* __restrict__ ids32) {
    extern __shared__ int sh[];              // [0,VOCAB) hist, [VOCAB,+1024) partials
    int* hist = sh;
    int* ssum = sh + VOCAB;
    int t = threadIdx.x;

    // int64/int32 sniff: ids < 32000 => int64 data has all odd words zero
    __shared__ int s_is64;
    if (t < 32) {
        unsigned nz = __ballot_sync(0xffffffffu, ids32[2 * t + 1] != 0);
        if (t == 0) s_is64 = (nz == 0u) ? 1 : 0;
    }

    // phase 0: zero hist
    #pragma unroll
    for (int i = 0; i < 32; i++) {
        int idx = t + i * SORT_THREADS;
        if (idx < VOCAB) hist[idx] = 0;
    }
    __syncthreads();
    int is64 = s_is64;

    // phase 1: count (coalesced id reads, smem atomics)
    int ids_local[32];
    #pragma unroll
    for (int i = 0; i < 32; i++) {
        int r = t + i * SORT_THREADS;        // 32 phases x 1024
        int id = is64 ? (int)((const long long*)ids32)[r] : ids32[r];
        ids_local[i] = id;
        atomicAdd(&hist[id], 1);
    }
    __syncthreads();

    // phase 2: scan — 32 bins per thread + Kogge-Stone over 1024 partials
    int cnt[32];
    int base = t * 32;                       // 1024*32 >= VOCAB
    int local = 0;
    #pragma unroll
    for (int i = 0; i < 32; i++) {
        int idx = base + i;
        cnt[i] = (idx < VOCAB) ? hist[idx] : 0;
        local += cnt[i];
    }
    ssum[t] = local;
    __syncthreads();
    for (int st = 1; st < SORT_THREADS; st <<= 1) {
        int v = (t >= st) ? ssum[t - st] : 0;
        __syncthreads();
        ssum[t] += v;
        __syncthreads();
    }
    int run = (t > 0) ? ssum[t - 1] : 0;     // exclusive prefix of this chunk
    #pragma unroll
    for (int i = 0; i < 32; i++) {
        int idx = base + i;
        if (idx < VOCAB) hist[idx] = run;
        run += cnt[i];
    }
    __syncthreads();

    // phase 3: scatter (smem atomics, packed perm)
    #pragma unroll
    for (int i = 0; i < 32; i++) {
        int r = t + i * SORT_THREADS;
        int id = ids_local[i];
        int pos = atomicAdd(&hist[id], 1);
        g_perm[pos] = (id << 15) | r;        // id < 2^15, r < 2^15
    }
}

// ---------------------------------------------------------------------------
// 5b. Embedding gather in id-sorted order: persistent grid-stride,
//     software-pipelined 2 rows/stage (next stage's loads issue before the
//     current stage's stores -> the DRAM read stream never drains).
//     Cached reads (adjacent duplicates hit L2), streaming stores.
// ---------------------------------------------------------------------------
#define GATHER_BLOCKS 1184   // 148 SMs x 8 launch slots (3 resident by regs)
__global__ void __launch_bounds__(256)
gather_kernel(const float* __restrict__ table, float* __restrict__ out) {
    int tid = threadIdx.x;
    const int STR = GATHER_BLOCKS * 2;
    int i = blockIdx.x * 2;              // always < NROWS (2366 < 32768)

    const float4 *s0, *s1;
    float4 *d0, *d1;
    float4 v[2][4];

    // prologue: pointers + first loads
    {
        int p0 = g_perm[i], p1 = g_perm[i + 1];
        s0 = (const float4*)(table + (size_t)(p0 >> 15) * DL);
        s1 = (const float4*)(table + (size_t)(p1 >> 15) * DL);
        int r0 = p0 & 32767, r1 = p1 & 32767;
        d0 = (float4*)(out + (size_t)((r0 >> 9) * OUT_S + TOPK + (r0 & 511)) * DL);
        d1 = (float4*)(out + (size_t)((r1 >> 9) * OUT_S + TOPK + (r1 & 511)) * DL);
        #pragma unroll
        for (int j = 0; j < 4; j++) {
            v[0][j] = s0[tid + j * 256];
            v[1][j] = s1[tid + j * 256];
        }
    }

    #pragma unroll 1
    while (true) {
        int nx = i + STR;
        bool has = (nx < NROWS);
        const float4 *ns0 = s0, *ns1 = s1;
        float4 *nd0 = d0, *nd1 = d1;
        float4 w[2][4];
        if (has) {
            int p0 = g_perm[nx], p1 = g_perm[nx + 1];
            ns0 = (const float4*)(table + (size_t)(p0 >> 15) * DL);
            ns1 = (const float4*)(table + (size_t)(p1 >> 15) * DL);
            int r0 = p0 & 32767, r1 = p1 & 32767;
            nd0 = (float4*)(out + (size_t)((r0 >> 9) * OUT_S + TOPK + (r0 & 511)) * DL);
            nd1 = (float4*)(out + (size_t)((r1 >> 9) * OUT_S + TOPK + (r1 & 511)) * DL);
            #pragma unroll
            for (int j = 0; j < 4; j++) {       // issue next loads FIRST
                w[0][j] = ns0[tid + j * 256];
                w[1][j] = ns1[tid + j * 256];
            }
        }
        // store current stage while next loads are in flight
        #pragma unroll
        for (int j = 0; j < 4; j++) {
            __stcs(d0 + tid + j * 256, v[0][j]);
            __stcs(d1 + tid + j * 256, v[1][j]);
        }
        if (!has) break;
        #pragma unroll
        for (int j = 0; j < 4; j++) { v[0][j] = w[0][j]; v[1][j] = w[1][j]; }
        s0 = ns0; s1 = ns1; d0 = nd0; d1 = nd1;
        i = nx;
    }
}

// ---------------------------------------------------------------------------
// kernel_launch: fork immediately; s2 = fused sort -> gather, s3 = convertB,
// main = scores -> topk -> convA -> (wait convertB) -> cp.async mma GEMM.
// metadata order: vision_tokens, input_ids, ln_gamma, ln_beta, scorer_w,
//                 scorer_b, proj_w, proj_b, embed_table
// ---------------------------------------------------------------------------
extern "C" void kernel_launch(void* const* d_in, const int* in_sizes, int n_in,
                              void* d_out, int out_size) {
    const float* vision_tokens = (const float*)d_in[0];
    const void*  input_ids     = d_in[1];
    const float* ln_gamma      = (const float*)d_in[2];
    const float* scorer_w      = (const float*)d_in[4];
    const float* proj_w        = (const float*)d_in[6];
    const float* proj_b        = (const float*)d_in[7];
    const float* embed_table   = (const float*)d_in[8];
    float* out = (float*)d_out;

    static cudaStream_t s2 = nullptr, s3 = nullptr;
    static cudaEvent_t eFork = nullptr, eB = nullptr, eG = nullptr;
    if (s2 == nullptr) {
        cudaStreamCreateWithFlags(&s2, cudaStreamNonBlocking);
        cudaStreamCreateWithFlags(&s3, cudaStreamNonBlocking);
        cudaEventCreateWithFlags(&eFork, cudaEventDisableTiming);
        cudaEventCreateWithFlags(&eB, cudaEventDisableTiming);
        cudaEventCreateWithFlags(&eG, cudaEventDisableTiming);
        cudaFuncSetAttribute(gemm_mma_kernel,
                             cudaFuncAttributeMaxDynamicSharedMemorySize, SMEM_TOTAL);
        cudaFuncSetAttribute(sort_kernel,
                             cudaFuncAttributeMaxDynamicSharedMemorySize, SORT_SMEM);
    }

    cudaEventRecord(eFork, 0);
    cudaStreamWaitEvent(s2, eFork, 0);
    cudaStreamWaitEvent(s3, eFork, 0);

    // stream s2: fused single-block counting sort, then the DRAM-bound gather
    const int* ids32 = (const int*)input_ids;
    sort_kernel<<<1, SORT_THREADS, SORT_SMEM, s2>>>(ids32);
    gather_kernel<<<GATHER_BLOCKS, 256, 0, s2>>>(embed_table, out);
    cudaEventRecord(eG, s2);

    // stream s3: B conversion for the GEMM
    {
        dim3 gb(DL / 32, DV / 32);    // 128 x 24
        convertB_kernel<<<gb, 256, 0, s3>>>(proj_w);
    }
    cudaEventRecord(eB, s3);

    // main stream: scoring chain -> GEMM
    scores_kernel<<<(B_SZ * P_SZ * 32 + 255) / 256, 256>>>(vision_tokens, ln_gamma, scorer_w);
    topk_kernel<<<(B_SZ * 32 + 255) / 256, 256>>>();
    convertA_kernel<<<M_TOT, 128>>>(vision_tokens);
    cudaStreamWaitEvent(0, eB, 0);
    gemm_mma_kernel<<<(M_TOT / TM) * (DL / TN), 256, SMEM_TOTAL>>>(proj_b, out);

    cudaStreamWaitEvent(0, eG, 0);
}